// round 4
// baseline (speedup 1.0000x reference)
#include <cuda_runtime.h>

// VolumeRenderer: fused NeRF-style compositing.
// depth [R,128] f32 (sorted, in [2,6]), density [R,128] f32 (in [0,1)),
// feature [R,128,3] f32 -> out [R,4] f32 (r,g,b,depth)
//
// R4: TWO rays per warp (half-warp segments of 16 lanes). Each lane owns 8
// consecutive samples -> 10 front-batched LDG.128 per lane (2x memory-level
// parallelism vs R3) and the shuffle scan/reduce shrink to 4 levels each
// (width=16 segmented), halving the serialized post-load tail per byte.
// Exclusive scan base via shfl_up(inclusive,1) to avoid fp32 cancellation
// against the 1e10 FAR_DELTA tau at the segment's last lane.

#define FULL 0xffffffffu

__global__ __launch_bounds__(256)
void vr_kernel(const float4* __restrict__ inA,   // depth OR density
               const float4* __restrict__ inB,   // the other one
               const float4* __restrict__ feature,
               float4* __restrict__ out,
               int n_rays)
{
    // Disambiguate depth vs density by value range (depth >= 2, density < 1).
    const float probe = ((const float*)inA)[0];
    const float4* __restrict__ depth   = (probe >= 2.0f) ? inA : inB;
    const float4* __restrict__ density = (probe >= 2.0f) ? inB : inA;

    const int warp = (blockIdx.x * blockDim.x + threadIdx.x) >> 5;
    const int lane = threadIdx.x & 31;
    const int seg  = lane & 15;                 // lane within 16-lane segment
    const int ray  = warp * 2 + (lane >> 4);    // 2 rays per warp
    if (ray >= n_rays) return;

    const size_t row32 = (size_t)ray * 32;   // 128 floats = 32 float4
    const size_t row96 = (size_t)ray * 96;   // 384 floats = 96 float4

    // Lane owns samples p = 8*seg .. 8*seg+7. Front-batch all 10 LDG.128.
    const float4* drow = depth   + row32 + seg * 2;
    const float4* nrow = density + row32 + seg * 2;
    const float4* frow = feature + row96 + seg * 6;
    float4 dep0 = __ldcs(drow + 0);   // {d0,d1,d2,d3}
    float4 dep1 = __ldcs(drow + 1);   // {d4,d5,d6,d7}
    float4 den0 = __ldcs(nrow + 0);
    float4 den1 = __ldcs(nrow + 1);
    float4 f0 = __ldcs(frow + 0);  // {p0r,p0g,p0b,p1r}
    float4 f1 = __ldcs(frow + 1);  // {p1g,p1b,p2r,p2g}
    float4 f2 = __ldcs(frow + 2);  // {p2b,p3r,p3g,p3b}
    float4 f3 = __ldcs(frow + 3);  // {p4r,p4g,p4b,p5r}
    float4 f4 = __ldcs(frow + 4);  // {p5g,p5b,p6r,p6g}
    float4 f5 = __ldcs(frow + 5);  // {p6b,p7r,p7g,p7b}

    // deltas; last sample of each ray (seg==15, sample 127) gets 1e10.
    // shfl_down crosses into the other segment at seg==15 / lane==31 but that
    // value is overridden by the sentinel.
    float nxt = __shfl_down_sync(FULL, dep0.x, 1);
    float t0 = den0.x * (dep0.y - dep0.x);
    float t1 = den0.y * (dep0.z - dep0.y);
    float t2 = den0.z * (dep0.w - dep0.z);
    float t3 = den0.w * (dep1.x - dep0.w);
    float t4 = den1.x * (dep1.y - dep1.x);
    float t5 = den1.y * (dep1.z - dep1.y);
    float t6 = den1.z * (dep1.w - dep1.z);
    float t7 = den1.w * ((seg == 15) ? 1e10f : (nxt - dep1.w));

    // per-lane inclusive prefix of tau
    float s0 = t0;
    float s1 = s0 + t1;
    float s2 = s1 + t2;
    float s3 = s2 + t3;
    float s4 = s3 + t4;
    float s5 = s4 + t5;
    float s6 = s5 + t6;
    float s7 = s6 + t7;   // seg 15: contains the 1e10 sentinel

    // segmented (width=16) inclusive scan of per-lane totals
    float v = s7;
    #pragma unroll
    for (int off = 1; off < 16; off <<= 1) {
        float n = __shfl_up_sync(FULL, v, off, 16);
        if (seg >= off) v += n;
    }
    // exclusive base = previous lane's inclusive value (no subtraction ->
    // no cancellation against the sentinel term)
    float base = __shfl_up_sync(FULL, v, 1, 16);
    if (seg == 0) base = 0.0f;

    // w_j = exp(-excl_j) - exp(-incl_j); 9 exps per lane
    float ep = __expf(-base);
    float e0 = __expf(-(base + s0));
    float e1 = __expf(-(base + s1));
    float e2 = __expf(-(base + s2));
    float e3 = __expf(-(base + s3));
    float e4 = __expf(-(base + s4));
    float e5 = __expf(-(base + s5));
    float e6 = __expf(-(base + s6));
    float e7 = __expf(-(base + s7));   // seg15: underflows to 0
    float w0 = ep - e0, w1 = e0 - e1, w2 = e1 - e2, w3 = e2 - e3;
    float w4 = e3 - e4, w5 = e4 - e5, w6 = e5 - e6, w7 = e6 - e7;

    // weighted accumulation (feature components per float4 packing)
    float r = w0*f0.x + w1*f0.w + w2*f1.z + w3*f2.y
            + w4*f3.x + w5*f3.w + w6*f4.z + w7*f5.y;
    float g = w0*f0.y + w1*f1.x + w2*f1.w + w3*f2.z
            + w4*f3.y + w5*f4.x + w6*f4.w + w7*f5.z;
    float b = w0*f0.z + w1*f1.y + w2*f2.x + w3*f2.w
            + w4*f3.z + w5*f4.y + w6*f5.x + w7*f5.w;
    float d = w0*dep0.x + w1*dep0.y + w2*dep0.z + w3*dep0.w
            + w4*dep1.x + w5*dep1.y + w6*dep1.z + w7*dep1.w;

    // segmented reduction (4 levels, width=16); two rays reduce in parallel
    #pragma unroll
    for (int off = 8; off > 0; off >>= 1) {
        r += __shfl_down_sync(FULL, r, off, 16);
        g += __shfl_down_sync(FULL, g, off, 16);
        b += __shfl_down_sync(FULL, b, off, 16);
        d += __shfl_down_sync(FULL, d, off, 16);
    }

    if (seg == 0) out[ray] = make_float4(r, g, b, d);
}

extern "C" void kernel_launch(void* const* d_in, const int* in_sizes, int n_in,
                              void* d_out, int out_size)
{
    // feature = the (unique) largest input; remaining two disambiguated
    // in-kernel by value range.
    int fi = 2;
    for (int i = 0; i < 3; ++i)
        if (in_sizes[i] > in_sizes[(i + 1) % 3] && in_sizes[i] > in_sizes[(i + 2) % 3]) fi = i;
    int a = (fi == 0) ? 1 : 0;
    int b = (fi == 2) ? 1 : 2;
    if (b == fi || b == a) b = 3 - a - fi;

    const float4* inA     = (const float4*)d_in[a];
    const float4* inB     = (const float4*)d_in[b];
    const float4* feature = (const float4*)d_in[fi];
    float4* out = (float4*)d_out;

    int n_rays = in_sizes[a] / 128;
    // 8 warps/block, 2 rays/warp -> 16 rays per 256-thread block
    int blocks = (n_rays + 15) / 16;
    vr_kernel<<<blocks, 256>>>(inA, inB, feature, out, n_rays);
}

// round 5
// speedup vs baseline: 1.2195x; 1.2195x over previous
#include <cuda_runtime.h>

// VolumeRenderer: fused NeRF-style compositing.
// depth [R,128] f32 (sorted, in [2,6]), density [R,128] f32 (in [0,1)),
// feature [R,128,3] f32 -> out [R,4] f32 (r,g,b,depth)
//
// R5: back to R3's winning shape (1 ray/warp, 31 regs, 8 blocks/SM = 100%
// theoretical occupancy -> max per-SM bytes in flight). R4 showed that
// raising per-warp MLP at the cost of occupancy LOWERS DRAM throughput.
// Changes vs R3:
//  - 4-component warp reduction in 11 shuffles instead of 20 (2 xor levels on
//    all 4 accumulators, then component-select by lane&3 + 3 xor levels).
//  - __ldcs streaming hints (no data reuse).
// Exclusive scan base via shfl_up(inclusive,1) to avoid fp32 cancellation
// against the 1e10 FAR_DELTA tau at lane 31.

#define FULL 0xffffffffu

__global__ __launch_bounds__(256, 8)
void vr_kernel(const float4* __restrict__ inA,   // depth OR density
               const float4* __restrict__ inB,   // the other one
               const float4* __restrict__ feature,
               float*  __restrict__ out,         // [R,4] flat
               int n_rays)
{
    // Disambiguate depth vs density by value range (depth >= 2, density < 1).
    const float probe = ((const float*)inA)[0];
    const float4* __restrict__ depth   = (probe >= 2.0f) ? inA : inB;
    const float4* __restrict__ density = (probe >= 2.0f) ? inB : inA;

    const int warp = (blockIdx.x * blockDim.x + threadIdx.x) >> 5;
    const int lane = threadIdx.x & 31;
    if (warp >= n_rays) return;

    const size_t row32 = (size_t)warp * 32;   // 128 floats = 32 float4
    const size_t row96 = (size_t)warp * 96;   // 384 floats = 96 float4

    // Lane owns samples p = 4*lane .. 4*lane+3 (5 front-batched LDG.128)
    float4 dep = __ldcs(depth   + row32 + lane);
    float4 den = __ldcs(density + row32 + lane);
    const float4* frow = feature + row96 + lane * 3;
    float4 f0 = __ldcs(frow + 0);  // {p0.r, p0.g, p0.b, p1.r}
    float4 f1 = __ldcs(frow + 1);  // {p1.g, p1.b, p2.r, p2.g}
    float4 f2 = __ldcs(frow + 2);  // {p2.b, p3.r, p3.g, p3.b}

    // deltas: depth[j+1]-depth[j]; last sample of the ray gets 1e10
    float nxt = __shfl_down_sync(FULL, dep.x, 1);
    float t0 = den.x * (dep.y - dep.x);
    float t1 = den.y * (dep.z - dep.y);
    float t2 = den.z * (dep.w - dep.z);
    float t3 = den.w * ((lane == 31) ? 1e10f : (nxt - dep.w));

    // per-lane inclusive prefix of tau
    float s0 = t0;
    float s1 = s0 + t1;
    float s2 = s1 + t2;
    float s3 = s2 + t3;   // lane 31: contains the 1e10 sentinel

    // warp inclusive scan of per-lane totals (Kogge-Stone)
    float v = s3;
    #pragma unroll
    for (int off = 1; off < 32; off <<= 1) {
        float n = __shfl_up_sync(FULL, v, off);
        if (lane >= off) v += n;
    }
    // exclusive base = previous lane's inclusive value (no subtraction ->
    // no cancellation against the sentinel term at lane 31)
    float base = __shfl_up_sync(FULL, v, 1);
    if (lane == 0) base = 0.0f;

    // w_j = exp(-excl_j) - exp(-incl_j); 5 exps per lane
    float ep = __expf(-base);
    float e0 = __expf(-(base + s0));
    float e1 = __expf(-(base + s1));
    float e2 = __expf(-(base + s2));
    float e3 = __expf(-(base + s3));   // lane31: underflows to 0
    float w0 = ep - e0, w1 = e0 - e1, w2 = e1 - e2, w3 = e2 - e3;

    // weighted accumulation (feature components per float4 packing)
    float r = w0*f0.x + w1*f0.w + w2*f1.z + w3*f2.y;
    float g = w0*f0.y + w1*f1.x + w2*f1.w + w3*f2.z;
    float b = w0*f0.z + w1*f1.y + w2*f2.x + w3*f2.w;
    float d = w0*dep.x + w1*dep.y + w2*dep.z + w3*dep.w;

    // 4-component reduction in 11 shuffles:
    // levels 1,2 on all four -> each 4-lane group holds its partials
    #pragma unroll
    for (int off = 1; off <= 2; off <<= 1) {
        r += __shfl_xor_sync(FULL, r, off);
        g += __shfl_xor_sync(FULL, g, off);
        b += __shfl_xor_sync(FULL, b, off);
        d += __shfl_xor_sync(FULL, d, off);
    }
    // each lane takes component (lane&3); 3 more levels finish all 4 sums
    int c = lane & 3;
    float val = (c == 0) ? r : (c == 1) ? g : (c == 2) ? b : d;
    #pragma unroll
    for (int off = 4; off < 32; off <<= 1)
        val += __shfl_xor_sync(FULL, val, off);

    // lanes 0..3 hold r,g,b,d totals -> one 16B line, 4 STG.32
    if (lane < 4) out[(size_t)warp * 4 + lane] = val;
}

extern "C" void kernel_launch(void* const* d_in, const int* in_sizes, int n_in,
                              void* d_out, int out_size)
{
    // feature = the (unique) largest input; remaining two disambiguated
    // in-kernel by value range.
    int fi = 2;
    for (int i = 0; i < 3; ++i)
        if (in_sizes[i] > in_sizes[(i + 1) % 3] && in_sizes[i] > in_sizes[(i + 2) % 3]) fi = i;
    int a = (fi == 0) ? 1 : 0;
    int b = (fi == 2) ? 1 : 2;
    if (b == fi || b == a) b = 3 - a - fi;

    const float4* inA     = (const float4*)d_in[a];
    const float4* inB     = (const float4*)d_in[b];
    const float4* feature = (const float4*)d_in[fi];
    float* out = (float*)d_out;

    int n_rays = in_sizes[a] / 128;
    int blocks = (n_rays + 7) / 8;   // 8 warps (rays) per 256-thread block
    vr_kernel<<<blocks, 256>>>(inA, inB, feature, out, n_rays);
}